// round 6
// baseline (speedup 1.0000x reference)
#include <cuda_runtime.h>
#include <cuda_bf16.h>
#include <cstdint>

typedef unsigned long long ull;

#define B_TOTAL 131072
#define T_STEPS 30
#define DIN     88
#define H       20
#define NGATE   80

// ================= GEMM (layer-0 input projection, HMMA) =================
#define M_ROWS   (B_TOTAL * T_STEPS)      // 3932160
#define M_TILE   128
#define N_TILES  (M_ROWS / M_TILE)        // 30720
#define G_CTA    128
#define KP       96                       // padded K per segment (88 -> 96)
#define AST      104                      // A smem row stride in bf16 (208 B)
#define BST      104                      // B smem row stride in bf16
#define CST      81                       // C stage row stride in f32

// smem byte offsets
#define SO_BIAS  0                        // 80 f32 permuted bias
#define SO_AHI   512                      // 128 x 104 bf16 = 26624
#define SO_ALO   (SO_AHI + 26624)         // 27136
#define SO_BHI   (SO_ALO + 26624)         // 53760
#define SO_BLO   (SO_BHI + 16640)         // 70400
#define G_SMEM   (SO_BLO + 16640)         // 87040
#define SO_CSTG  512                      // C stage reuses A region after compute

// 1.26 GB scratch for xg[b*T + t][80] (permuted gate order), fp32
__device__ float g_xg[(size_t)M_ROWS * NGATE];

// ---------------- helpers ----------------
__device__ __forceinline__ void split4(float4 f, ull& hi4, ull& lo4) {
    __nv_bfloat16 hx = __float2bfloat16_rn(f.x);
    __nv_bfloat16 hy = __float2bfloat16_rn(f.y);
    __nv_bfloat16 hz = __float2bfloat16_rn(f.z);
    __nv_bfloat16 hw = __float2bfloat16_rn(f.w);
    __nv_bfloat16 lx = __float2bfloat16_rn(f.x - __bfloat162float(hx));
    __nv_bfloat16 ly = __float2bfloat16_rn(f.y - __bfloat162float(hy));
    __nv_bfloat16 lz = __float2bfloat16_rn(f.z - __bfloat162float(hz));
    __nv_bfloat16 lw = __float2bfloat16_rn(f.w - __bfloat162float(hw));
    hi4 = (ull)__bfloat16_as_ushort(hx) | ((ull)__bfloat16_as_ushort(hy) << 16)
        | ((ull)__bfloat16_as_ushort(hz) << 32) | ((ull)__bfloat16_as_ushort(hw) << 48);
    lo4 = (ull)__bfloat16_as_ushort(lx) | ((ull)__bfloat16_as_ushort(ly) << 16)
        | ((ull)__bfloat16_as_ushort(lz) << 32) | ((ull)__bfloat16_as_ushort(lw) << 48);
}

__device__ __forceinline__ void mma16816(float* d,
                                         uint32_t a0, uint32_t a1, uint32_t a2, uint32_t a3,
                                         uint32_t b0, uint32_t b1) {
    asm volatile(
        "mma.sync.aligned.m16n8k16.row.col.f32.bf16.bf16.f32 "
        "{%0,%1,%2,%3}, {%4,%5,%6,%7}, {%8,%9}, {%0,%1,%2,%3};"
        : "+f"(d[0]), "+f"(d[1]), "+f"(d[2]), "+f"(d[3])
        : "r"(a0), "r"(a1), "r"(a2), "r"(a3), "r"(b0), "r"(b1));
}

// permuted gate index: recurrent layout j -> natural gate row
__device__ __forceinline__ int perm_gate(int j) {
    int v = j / 20, o = j % 20;
    return (o / 5) * 20 + v * 5 + (o % 5);
}

// ---------------- GEMM kernel: one 128-row tile per CTA ----------------
__global__ void __launch_bounds__(G_CTA, 2)
xg_gemm_kernel(const float* __restrict__ x, const float* __restrict__ Wih0,
               const float* __restrict__ bih0, const float* __restrict__ bhh0)
{
    extern __shared__ char smem[];
    const int tid = threadIdx.x;
    const int warp = tid >> 5, lane = tid & 31;
    const int gid = lane >> 2, tg = lane & 3;   // groupID / threadInGroup
    const int tile = blockIdx.x;

    // ---- permuted bias ----
    if (tid < NGATE) {
        int g = perm_gate(tid);
        ((float*)(smem + SO_BIAS))[tid] = bih0[g] + bhh0[g];
    }

    // ---- stage A: thread = row; split fp32 -> bf16 hi/lo ----
    {
        char* ahi = smem + SO_AHI + tid * (AST * 2);
        char* alo = smem + SO_ALO + tid * (AST * 2);
        const float4* xr = (const float4*)(x + (size_t)(tile * M_TILE + tid) * DIN);
        #pragma unroll 1
        for (int q = 0; q < DIN / 4; q++) {
            ull hi4, lo4;
            split4(xr[q], hi4, lo4);
            *(ull*)(ahi + q * 8) = hi4;
            *(ull*)(alo + q * 8) = lo4;
        }
        // zero pad cols 88..95
        *(ull*)(ahi + 176) = 0; *(ull*)(ahi + 184) = 0;
        *(ull*)(alo + 176) = 0; *(ull*)(alo + 184) = 0;
    }
    // ---- stage B: thread = gate row (0..79) ----
    if (tid < NGATE) {
        char* bhi = smem + SO_BHI + tid * (BST * 2);
        char* blo = smem + SO_BLO + tid * (BST * 2);
        const float4* wr = (const float4*)(Wih0 + tid * DIN);
        #pragma unroll 1
        for (int q = 0; q < DIN / 4; q++) {
            ull hi4, lo4;
            split4(wr[q], hi4, lo4);
            *(ull*)(bhi + q * 8) = hi4;
            *(ull*)(blo + q * 8) = lo4;
        }
        *(ull*)(bhi + 176) = 0; *(ull*)(bhi + 184) = 0;
        *(ull*)(blo + 176) = 0; *(ull*)(blo + 184) = 0;
    }
    __syncthreads();

    // ---- mainloop: 18 k16 steps, 3 bf16-split segments ----
    float c[2][10][4];
    #pragma unroll
    for (int mf = 0; mf < 2; mf++)
        #pragma unroll
        for (int nf = 0; nf < 10; nf++)
            #pragma unroll
            for (int q = 0; q < 4; q++) c[mf][nf][q] = 0.f;

    #pragma unroll 1
    for (int s = 0; s < 18; s++) {
        const char* As = smem + ((s < 12) ? SO_AHI : SO_ALO);
        const char* Bs = smem + ((s < 6) ? SO_BHI : (s < 12 ? SO_BLO : SO_BHI));
        const int ko = (s % 6) * 16;

        uint32_t bf[10][2];
        #pragma unroll
        for (int nf = 0; nf < 10; nf++) {
            int n = nf * 8 + gid;
            const char* bp = Bs + n * (BST * 2) + (ko + tg * 2) * 2;
            bf[nf][0] = *(const uint32_t*)(bp);
            bf[nf][1] = *(const uint32_t*)(bp + 16);
        }
        #pragma unroll
        for (int mf = 0; mf < 2; mf++) {
            int m = warp * 32 + mf * 16 + gid;
            const char* ap0 = As + m * (AST * 2) + (ko + tg * 2) * 2;
            const char* ap1 = ap0 + 8 * (AST * 2);
            uint32_t a0 = *(const uint32_t*)(ap0);
            uint32_t a1 = *(const uint32_t*)(ap1);
            uint32_t a2 = *(const uint32_t*)(ap0 + 16);
            uint32_t a3 = *(const uint32_t*)(ap1 + 16);
            #pragma unroll
            for (int nf = 0; nf < 10; nf++)
                mma16816(c[mf][nf], a0, a1, a2, a3, bf[nf][0], bf[nf][1]);
        }
    }
    __syncthreads();   // A/B smem now reusable as C stage

    // ---- epilogue: frags -> smem, permuted+bias read, STG.128 ----
    char* cstg = smem + SO_CSTG + warp * (32 * CST * 4);
    #pragma unroll
    for (int mf = 0; mf < 2; mf++) {
        #pragma unroll
        for (int nf = 0; nf < 10; nf++) {
            float* r0 = (float*)(cstg + (((mf * 16 + gid) * CST) + nf * 8 + tg * 2) * 4);
            float* r1 = (float*)(cstg + (((mf * 16 + gid + 8) * CST) + nf * 8 + tg * 2) * 4);
            r0[0] = c[mf][nf][0]; r0[1] = c[mf][nf][1];
            r1[0] = c[mf][nf][2]; r1[1] = c[mf][nf][3];
        }
    }
    __syncwarp();
    {
        const float* src  = (const float*)(cstg + lane * (CST * 4));
        const float* bias = (const float*)(smem + SO_BIAS);
        float4* dst = (float4*)(g_xg + (size_t)(tile * M_TILE + warp * 32 + lane) * NGATE);
        #pragma unroll
        for (int j4 = 0; j4 < 20; j4++) {
            float t_[4];
            #pragma unroll
            for (int q = 0; q < 4; q++) {
                int j = j4 * 4 + q;
                t_[q] = src[perm_gate(j)] + bias[j];
            }
            dst[j4] = make_float4(t_[0], t_[1], t_[2], t_[3]);
        }
    }
}

// ================= recurrent kernel =================
#define CTA     128
#define HS_STR  33

struct __align__(16) SMR {
    float w0h[H * 80];
    float w1x[H * 80];
    float w1h[H * 80];
    float bias1[80];
    float wfc[2 * H];
    float bfc[2];
    float4 hs0[H * HS_STR];
    float4 hs1[H * HS_STR];
};

__device__ __forceinline__ ull ffma2(ull a, ull b, ull c) {
    ull d;
    asm("fma.rn.f32x2 %0, %1, %2, %3;" : "=l"(d) : "l"(a), "l"(b), "l"(c));
    return d;
}
__device__ __forceinline__ ull pack2(float x) {
    ull r;
    asm("mov.b64 %0, {%1, %1};" : "=l"(r) : "f"(x));
    return r;
}
__device__ __forceinline__ ull packxy(float x, float y) {
    ull r;
    asm("mov.b64 %0, {%1, %2};" : "=l"(r) : "f"(x), "f"(y));
    return r;
}
__device__ __forceinline__ float getf(const ull* acc, int idx) {
    ull v = acc[idx >> 1];
    unsigned u = (idx & 1) ? (unsigned)(v >> 32) : (unsigned)(v & 0xffffffffu);
    return __uint_as_float(u);
}
__device__ __forceinline__ float sig_(float x) {
    return __fdividef(1.0f, 1.0f + __expf(-x));
}
__device__ __forceinline__ float tanh_(float x) {
    float a = fabsf(x);
    float e = __expf(a + a);
    float r = 1.0f - __fdividef(2.0f, e + 1.0f);
    return copysignf(r, x);
}
__device__ __forceinline__ void accum4(ull* a, const ulonglong2* __restrict__ w,
                                       ull x0, ull x1, ull x2, ull x3) {
    #pragma unroll
    for (int c = 0; c < 5; c++) {
        ulonglong2 wc = w[c];
        a[ 0 + 2*c]   = ffma2(wc.x, x0, a[ 0 + 2*c]);
        a[ 0 + 2*c+1] = ffma2(wc.y, x0, a[ 0 + 2*c+1]);
        a[10 + 2*c]   = ffma2(wc.x, x1, a[10 + 2*c]);
        a[10 + 2*c+1] = ffma2(wc.y, x1, a[10 + 2*c+1]);
        a[20 + 2*c]   = ffma2(wc.x, x2, a[20 + 2*c]);
        a[20 + 2*c+1] = ffma2(wc.y, x2, a[20 + 2*c+1]);
        a[30 + 2*c]   = ffma2(wc.x, x3, a[30 + 2*c]);
        a[30 + 2*c+1] = ffma2(wc.y, x3, a[30 + 2*c+1]);
    }
}

__global__ void __launch_bounds__(CTA, 3) lstm2_rec_kernel(
    const float* __restrict__ Whh0,
    const float* __restrict__ Wih1, const float* __restrict__ Whh1,
    const float* __restrict__ bih1, const float* __restrict__ bhh1,
    const float* __restrict__ Wfc,  const float* __restrict__ bfc,
    float* __restrict__ out)
{
    extern __shared__ unsigned char smraw[];
    SMR* sm = reinterpret_cast<SMR*>(smraw);
    const int tid = threadIdx.x;

    #pragma unroll 1
    for (int idx = tid; idx < H * 80; idx += CTA) {
        int d = idx / 80, rem = idx - d * 80;
        int v = rem / 20, o = rem - v * 20;
        int row = (o / 5) * 20 + v * 5 + (o % 5);
        sm->w0h[idx] = Whh0[row * H + d];
        sm->w1x[idx] = Wih1[row * H + d];
        sm->w1h[idx] = Whh1[row * H + d];
    }
    if (tid < 80) {
        int v = tid / 20, o = tid - v * 20;
        int row = (o / 5) * 20 + v * 5 + (o % 5);
        sm->bias1[tid] = bih1[row] + bhh1[row];
    }
    if (tid < 2 * H) sm->wfc[tid] = Wfc[tid];
    if (tid < 2)     sm->bfc[tid] = bfc[tid];

    const int g = tid >> 2;
    const int v = tid & 3;

    #pragma unroll
    for (int ul = 0; ul < 5; ul++) {
        sm->hs0[(v * 5 + ul) * HS_STR + g] = make_float4(0.f, 0.f, 0.f, 0.f);
        sm->hs1[(v * 5 + ul) * HS_STR + g] = make_float4(0.f, 0.f, 0.f, 0.f);
    }
    __syncthreads();

    const int bg = blockIdx.x * CTA + g * 4;
    const float* xg0 = g_xg + ((size_t)(bg + 0) * T_STEPS) * NGATE + v * 20;
    const float* xg1 = g_xg + ((size_t)(bg + 1) * T_STEPS) * NGATE + v * 20;
    const float* xg2 = g_xg + ((size_t)(bg + 2) * T_STEPS) * NGATE + v * 20;
    const float* xg3 = g_xg + ((size_t)(bg + 3) * T_STEPS) * NGATE + v * 20;

    const ulonglong2* w0h = reinterpret_cast<const ulonglong2*>(sm->w0h);
    const ulonglong2* w1x = reinterpret_cast<const ulonglong2*>(sm->w1x);
    const ulonglong2* w1h = reinterpret_cast<const ulonglong2*>(sm->w1h);
    const ulonglong2* bias1 = reinterpret_cast<const ulonglong2*>(sm->bias1) + v * 5;
    float4* hs0 = sm->hs0;
    float4* hs1 = sm->hs1;

    float c0[20], c1[20];
    #pragma unroll
    for (int i = 0; i < 20; i++) { c0[i] = 0.f; c1[i] = 0.f; }

    ull a[40];

    #pragma unroll 1
    for (int t = 0; t < T_STEPS; t++) {
        // ===== layer 0: acc = xg (bias folded in GEMM) =====
        {
            const float4* p0 = (const float4*)(xg0 + t * NGATE);
            const float4* p1 = (const float4*)(xg1 + t * NGATE);
            const float4* p2 = (const float4*)(xg2 + t * NGATE);
            const float4* p3 = (const float4*)(xg3 + t * NGATE);
            #pragma unroll
            for (int u = 0; u < 5; u++) {
                float4 q0 = p0[u], q1 = p1[u], q2 = p2[u], q3 = p3[u];
                a[      2*u] = packxy(q0.x, q0.y); a[      2*u+1] = packxy(q0.z, q0.w);
                a[10 +  2*u] = packxy(q1.x, q1.y); a[10 +  2*u+1] = packxy(q1.z, q1.w);
                a[20 +  2*u] = packxy(q2.x, q2.y); a[20 +  2*u+1] = packxy(q2.z, q2.w);
                a[30 +  2*u] = packxy(q3.x, q3.y); a[30 +  2*u+1] = packxy(q3.z, q3.w);
            }
        }
        #pragma unroll 4
        for (int k = 0; k < H; k++) {
            float4 hv = hs0[k * HS_STR + g];
            accum4(a, w0h + k * 20 + v * 5,
                   pack2(hv.x), pack2(hv.y), pack2(hv.z), pack2(hv.w));
        }
        #pragma unroll
        for (int ul = 0; ul < 5; ul++) {
            float hv[4];
            #pragma unroll
            for (int e = 0; e < 4; e++) {
                const ull* ae = a + e * 10;
                float iv = sig_ (getf(ae,      ul));
                float fv = sig_ (getf(ae,  5 + ul));
                float gv = tanh_(getf(ae, 10 + ul));
                float ov = sig_ (getf(ae, 15 + ul));
                float cn = fv * c0[e*5 + ul] + iv * gv;
                c0[e*5 + ul] = cn;
                hv[e] = ov * tanh_(cn);
            }
            hs0[(v * 5 + ul) * HS_STR + g] = make_float4(hv[0], hv[1], hv[2], hv[3]);
        }
        __syncwarp();

        // ===== layer 1 =====
        #pragma unroll
        for (int c = 0; c < 5; c++) {
            ulonglong2 bb = bias1[c];
            a[2*c] = bb.x; a[2*c+1] = bb.y;
            a[10+2*c] = bb.x; a[10+2*c+1] = bb.y;
            a[20+2*c] = bb.x; a[20+2*c+1] = bb.y;
            a[30+2*c] = bb.x; a[30+2*c+1] = bb.y;
        }
        #pragma unroll 4
        for (int k = 0; k < H; k++) {
            float4 hv = hs0[k * HS_STR + g];
            accum4(a, w1x + k * 20 + v * 5,
                   pack2(hv.x), pack2(hv.y), pack2(hv.z), pack2(hv.w));
        }
        #pragma unroll 4
        for (int k = 0; k < H; k++) {
            float4 hv = hs1[k * HS_STR + g];
            accum4(a, w1h + k * 20 + v * 5,
                   pack2(hv.x), pack2(hv.y), pack2(hv.z), pack2(hv.w));
        }
        #pragma unroll
        for (int ul = 0; ul < 5; ul++) {
            float hv[4];
            #pragma unroll
            for (int e = 0; e < 4; e++) {
                const ull* ae = a + e * 10;
                float iv = sig_ (getf(ae,      ul));
                float fv = sig_ (getf(ae,  5 + ul));
                float gv = tanh_(getf(ae, 10 + ul));
                float ov = sig_ (getf(ae, 15 + ul));
                float cn = fv * c1[e*5 + ul] + iv * gv;
                c1[e*5 + ul] = cn;
                hv[e] = ov * tanh_(cn);
            }
            hs1[(v * 5 + ul) * HS_STR + g] = make_float4(hv[0], hv[1], hv[2], hv[3]);
        }
        __syncwarp();
    }

    // ---- FC + softmax(2) ----
    float l0 = sm->bfc[0], l1 = sm->bfc[1];
    #pragma unroll
    for (int k = 0; k < H; k++) {
        float4 hq = hs1[k * HS_STR + g];
        float hk = (v == 0) ? hq.x : (v == 1) ? hq.y : (v == 2) ? hq.z : hq.w;
        l0 += sm->wfc[k]     * hk;
        l1 += sm->wfc[H + k] * hk;
    }
    float p0 = sig_(l0 - l1);
    reinterpret_cast<float2*>(out)[bg + v] = make_float2(p0, 1.0f - p0);
}

// ---------------- launch ----------------
extern "C" void kernel_launch(void* const* d_in, const int* in_sizes, int n_in,
                              void* d_out, int out_size) {
    const float* x    = (const float*)d_in[0];
    const float* Wih0 = (const float*)d_in[1];
    const float* Whh0 = (const float*)d_in[2];
    const float* bih0 = (const float*)d_in[3];
    const float* bhh0 = (const float*)d_in[4];
    const float* Wih1 = (const float*)d_in[5];
    const float* Whh1 = (const float*)d_in[6];
    const float* bih1 = (const float*)d_in[7];
    const float* bhh1 = (const float*)d_in[8];
    const float* Wfc  = (const float*)d_in[9];
    const float* bfc  = (const float*)d_in[10];
    float* out = (float*)d_out;

    cudaFuncSetAttribute(xg_gemm_kernel, cudaFuncAttributeMaxDynamicSharedMemorySize, G_SMEM);
    xg_gemm_kernel<<<N_TILES, G_CTA, G_SMEM>>>(x, Wih0, bih0, bhh0);

    const size_t smem2 = sizeof(SMR);
    cudaFuncSetAttribute(lstm2_rec_kernel, cudaFuncAttributeMaxDynamicSharedMemorySize, (int)smem2);
    lstm2_rec_kernel<<<B_TOTAL / CTA, CTA, smem2>>>(
        Whh0, Wih1, Whh1, bih1, bhh1, Wfc, bfc, out);
}

// round 8
// speedup vs baseline: 1.3643x; 1.3643x over previous
#include <cuda_runtime.h>
#include <cuda_bf16.h>
#include <cstdint>

typedef unsigned long long ull;

#define B_TOTAL 131072
#define T_STEPS 30
#define DIN     88
#define H       20
#define NGATE   80

// ================= GEMM (layer-0 input projection, HMMA, persistent) =================
#define M_ROWS   (B_TOTAL * T_STEPS)      // 3932160
#define M_TILE   128
#define N_TILES  (M_ROWS / M_TILE)        // 30720
#define G_GRID   296                      // 2 CTAs/SM persistent
#define G_CTA    128
#define AST      104                      // A smem row stride in bf16 (208 B)
#define BST      104
#define CST      81                       // C stage row stride in f32

// smem byte offsets
#define SO_BIAS  0                        // 80 f32 permuted bias (pad to 512)
#define SO_AHI   512                      // 128 x 104 bf16 = 26624
#define SO_ALO   (SO_AHI + 26624)         // 27136
#define SO_BHI   (SO_ALO + 26624)         // 53760
#define SO_BLO   (SO_BHI + 16640)         // 70400
#define G_SMEM   (SO_BLO + 16640)         // 87040  (2 CTAs/SM = 174KB)
#define SO_CSTG  SO_AHI                   // C stage aliases A (dead after MMA sync)

// 1.26 GB scratch for xg[b*T + t][80] (permuted gate order), fp32
__device__ float g_xg[(size_t)M_ROWS * NGATE];

// ---------------- helpers ----------------
__device__ __forceinline__ void split4(float4 f, ull& hi4, ull& lo4) {
    __nv_bfloat16 hx = __float2bfloat16_rn(f.x);
    __nv_bfloat16 hy = __float2bfloat16_rn(f.y);
    __nv_bfloat16 hz = __float2bfloat16_rn(f.z);
    __nv_bfloat16 hw = __float2bfloat16_rn(f.w);
    __nv_bfloat16 lx = __float2bfloat16_rn(f.x - __bfloat162float(hx));
    __nv_bfloat16 ly = __float2bfloat16_rn(f.y - __bfloat162float(hy));
    __nv_bfloat16 lz = __float2bfloat16_rn(f.z - __bfloat162float(hz));
    __nv_bfloat16 lw = __float2bfloat16_rn(f.w - __bfloat162float(hw));
    hi4 = (ull)__bfloat16_as_ushort(hx) | ((ull)__bfloat16_as_ushort(hy) << 16)
        | ((ull)__bfloat16_as_ushort(hz) << 32) | ((ull)__bfloat16_as_ushort(hw) << 48);
    lo4 = (ull)__bfloat16_as_ushort(lx) | ((ull)__bfloat16_as_ushort(ly) << 16)
        | ((ull)__bfloat16_as_ushort(lz) << 32) | ((ull)__bfloat16_as_ushort(lw) << 48);
}

__device__ __forceinline__ void mma16816(float* d,
                                         uint32_t a0, uint32_t a1, uint32_t a2, uint32_t a3,
                                         uint32_t b0, uint32_t b1) {
    asm volatile(
        "mma.sync.aligned.m16n8k16.row.col.f32.bf16.bf16.f32 "
        "{%0,%1,%2,%3}, {%4,%5,%6,%7}, {%8,%9}, {%0,%1,%2,%3};"
        : "+f"(d[0]), "+f"(d[1]), "+f"(d[2]), "+f"(d[3])
        : "r"(a0), "r"(a1), "r"(a2), "r"(a3), "r"(b0), "r"(b1));
}

__device__ __forceinline__ int perm_gate(int j) {
    int v = j / 20, o = j % 20;
    return (o / 5) * 20 + v * 5 + (o % 5);
}

// ---------------- persistent GEMM kernel ----------------
__global__ void __launch_bounds__(G_CTA, 2)
xg_gemm_kernel(const float* __restrict__ x, const float* __restrict__ Wih0,
               const float* __restrict__ bih0, const float* __restrict__ bhh0)
{
    extern __shared__ char smem[];
    const int tid = threadIdx.x;
    const int warp = tid >> 5, lane = tid & 31;
    const int gid = lane >> 2, tg = lane & 3;

    // ---- one-time: permuted bias + B hi/lo staging ----
    if (tid < NGATE) {
        int g = perm_gate(tid);
        ((float*)(smem + SO_BIAS))[tid] = bih0[g] + bhh0[g];

        char* bhi = smem + SO_BHI + tid * (BST * 2);
        char* blo = smem + SO_BLO + tid * (BST * 2);
        const float4* wr = (const float4*)(Wih0 + tid * DIN);
        float4 wv[22];
        #pragma unroll
        for (int q = 0; q < 22; q++) wv[q] = wr[q];
        #pragma unroll
        for (int q = 0; q < 22; q++) {
            ull hi4, lo4;
            split4(wv[q], hi4, lo4);
            *(ull*)(bhi + q * 8) = hi4;
            *(ull*)(blo + q * 8) = lo4;
        }
        *(ull*)(bhi + 176) = 0; *(ull*)(bhi + 184) = 0;
        *(ull*)(blo + 176) = 0; *(ull*)(blo + 184) = 0;
    }

    // ---- prefetch first tile's row into registers ----
    int tile = blockIdx.x;
    float4 xr[22];
    if (tile < N_TILES) {
        const float4* xp = (const float4*)(x + (size_t)(tile * M_TILE + tid) * DIN);
        #pragma unroll
        for (int q = 0; q < 22; q++) xr[q] = xp[q];
    }
    __syncthreads();

    char* const ahi = smem + SO_AHI + tid * (AST * 2);
    char* const alo = smem + SO_ALO + tid * (AST * 2);

    #pragma unroll 1
    for (; tile < N_TILES; tile += G_GRID) {
        // ---- phase 1: convert + store A (regs hold this tile's row) ----
        #pragma unroll
        for (int q = 0; q < 22; q++) {
            ull hi4, lo4;
            split4(xr[q], hi4, lo4);
            *(ull*)(ahi + q * 8) = hi4;
            *(ull*)(alo + q * 8) = lo4;
        }
        // pads (C-stage alias may have clobbered them)
        *(ull*)(ahi + 176) = 0; *(ull*)(ahi + 184) = 0;
        *(ull*)(alo + 176) = 0; *(ull*)(alo + 184) = 0;
        __syncthreads();

        // ---- phase 2: prefetch next tile (overlaps MMA below) ----
        {
            int nxt = tile + G_GRID;
            if (nxt < N_TILES) {
                const float4* xp = (const float4*)(x + (size_t)(nxt * M_TILE + tid) * DIN);
                #pragma unroll
                for (int q = 0; q < 22; q++) xr[q] = xp[q];
            }
        }

        // ---- MMA mainloop: 18 k16 steps, 3 bf16-split segments ----
        float c[2][10][4];
        #pragma unroll
        for (int mf = 0; mf < 2; mf++)
            #pragma unroll
            for (int nf = 0; nf < 10; nf++)
                #pragma unroll
                for (int q = 0; q < 4; q++) c[mf][nf][q] = 0.f;

        #pragma unroll 1
        for (int s = 0; s < 18; s++) {
            const char* As = smem + ((s < 12) ? SO_AHI : SO_ALO);
            const char* Bs = smem + ((s < 6) ? SO_BHI : (s < 12 ? SO_BLO : SO_BHI));
            const int ko = (s % 6) * 16;

            uint32_t bf[10][2];
            #pragma unroll
            for (int nf = 0; nf < 10; nf++) {
                int n = nf * 8 + gid;
                const char* bp = Bs + n * (BST * 2) + (ko + tg * 2) * 2;
                bf[nf][0] = *(const uint32_t*)(bp);
                bf[nf][1] = *(const uint32_t*)(bp + 16);
            }
            #pragma unroll
            for (int mf = 0; mf < 2; mf++) {
                int m = warp * 32 + mf * 16 + gid;
                const char* ap0 = As + m * (AST * 2) + (ko + tg * 2) * 2;
                const char* ap1 = ap0 + 8 * (AST * 2);
                uint32_t a0 = *(const uint32_t*)(ap0);
                uint32_t a1 = *(const uint32_t*)(ap1);
                uint32_t a2 = *(const uint32_t*)(ap0 + 16);
                uint32_t a3 = *(const uint32_t*)(ap1 + 16);
                #pragma unroll
                for (int nf = 0; nf < 10; nf++)
                    mma16816(c[mf][nf], a0, a1, a2, a3, bf[nf][0], bf[nf][1]);
            }
        }
        __syncthreads();   // all warps done reading A -> safe to alias as C stage

        // ---- epilogue: frags -> smem (warp-private), permuted+bias, STG.128 ----
        char* cstg = smem + SO_CSTG + warp * (32 * CST * 4);
        #pragma unroll
        for (int mf = 0; mf < 2; mf++) {
            #pragma unroll
            for (int nf = 0; nf < 10; nf++) {
                float* r0 = (float*)(cstg + (((mf * 16 + gid) * CST) + nf * 8 + tg * 2) * 4);
                float* r1 = (float*)(cstg + (((mf * 16 + gid + 8) * CST) + nf * 8 + tg * 2) * 4);
                r0[0] = c[mf][nf][0]; r0[1] = c[mf][nf][1];
                r1[0] = c[mf][nf][2]; r1[1] = c[mf][nf][3];
            }
        }
        __syncwarp();
        {
            const float* src  = (const float*)(cstg + lane * (CST * 4));
            const float* bias = (const float*)(smem + SO_BIAS);
            float4* dst = (float4*)(g_xg + (size_t)(tile * M_TILE + warp * 32 + lane) * NGATE);
            #pragma unroll
            for (int j4 = 0; j4 < 20; j4++) {
                float t_[4];
                #pragma unroll
                for (int q = 0; q < 4; q++) {
                    int j = j4 * 4 + q;
                    t_[q] = src[perm_gate(j)] + bias[j];
                }
                dst[j4] = make_float4(t_[0], t_[1], t_[2], t_[3]);
            }
        }
        __syncthreads();   // epilogue reads done before next tile's A store
    }
}

// ================= recurrent kernel (EXACT R6 version, 1014us measured) =================
#define CTA     128
#define HS_STR  33

struct __align__(16) SMR {
    float w0h[H * 80];
    float w1x[H * 80];
    float w1h[H * 80];
    float bias1[80];
    float wfc[2 * H];
    float bfc[2];
    float4 hs0[H * HS_STR];
    float4 hs1[H * HS_STR];
};

__device__ __forceinline__ ull ffma2(ull a, ull b, ull c) {
    ull d;
    asm("fma.rn.f32x2 %0, %1, %2, %3;" : "=l"(d) : "l"(a), "l"(b), "l"(c));
    return d;
}
__device__ __forceinline__ ull pack2(float x) {
    ull r;
    asm("mov.b64 %0, {%1, %1};" : "=l"(r) : "f"(x));
    return r;
}
__device__ __forceinline__ ull packxy(float x, float y) {
    ull r;
    asm("mov.b64 %0, {%1, %2};" : "=l"(r) : "f"(x), "f"(y));
    return r;
}
__device__ __forceinline__ float getf(const ull* acc, int idx) {
    ull v = acc[idx >> 1];
    unsigned u = (idx & 1) ? (unsigned)(v >> 32) : (unsigned)(v & 0xffffffffu);
    return __uint_as_float(u);
}
__device__ __forceinline__ float sig_(float x) {
    return __fdividef(1.0f, 1.0f + __expf(-x));
}
__device__ __forceinline__ float tanh_(float x) {
    float a = fabsf(x);
    float e = __expf(a + a);
    float r = 1.0f - __fdividef(2.0f, e + 1.0f);
    return copysignf(r, x);
}
__device__ __forceinline__ void accum4(ull* a, const ulonglong2* __restrict__ w,
                                       ull x0, ull x1, ull x2, ull x3) {
    #pragma unroll
    for (int c = 0; c < 5; c++) {
        ulonglong2 wc = w[c];
        a[ 0 + 2*c]   = ffma2(wc.x, x0, a[ 0 + 2*c]);
        a[ 0 + 2*c+1] = ffma2(wc.y, x0, a[ 0 + 2*c+1]);
        a[10 + 2*c]   = ffma2(wc.x, x1, a[10 + 2*c]);
        a[10 + 2*c+1] = ffma2(wc.y, x1, a[10 + 2*c+1]);
        a[20 + 2*c]   = ffma2(wc.x, x2, a[20 + 2*c]);
        a[20 + 2*c+1] = ffma2(wc.y, x2, a[20 + 2*c+1]);
        a[30 + 2*c]   = ffma2(wc.x, x3, a[30 + 2*c]);
        a[30 + 2*c+1] = ffma2(wc.y, x3, a[30 + 2*c+1]);
    }
}

__global__ void __launch_bounds__(CTA, 3) lstm2_rec_kernel(
    const float* __restrict__ Whh0,
    const float* __restrict__ Wih1, const float* __restrict__ Whh1,
    const float* __restrict__ bih1, const float* __restrict__ bhh1,
    const float* __restrict__ Wfc,  const float* __restrict__ bfc,
    float* __restrict__ out)
{
    extern __shared__ unsigned char smraw[];
    SMR* sm = reinterpret_cast<SMR*>(smraw);
    const int tid = threadIdx.x;

    #pragma unroll 1
    for (int idx = tid; idx < H * 80; idx += CTA) {
        int d = idx / 80, rem = idx - d * 80;
        int v = rem / 20, o = rem - v * 20;
        int row = (o / 5) * 20 + v * 5 + (o % 5);
        sm->w0h[idx] = Whh0[row * H + d];
        sm->w1x[idx] = Wih1[row * H + d];
        sm->w1h[idx] = Whh1[row * H + d];
    }
    if (tid < 80) {
        int v = tid / 20, o = tid - v * 20;
        int row = (o / 5) * 20 + v * 5 + (o % 5);
        sm->bias1[tid] = bih1[row] + bhh1[row];
    }
    if (tid < 2 * H) sm->wfc[tid] = Wfc[tid];
    if (tid < 2)     sm->bfc[tid] = bfc[tid];

    const int g = tid >> 2;
    const int v = tid & 3;

    #pragma unroll
    for (int ul = 0; ul < 5; ul++) {
        sm->hs0[(v * 5 + ul) * HS_STR + g] = make_float4(0.f, 0.f, 0.f, 0.f);
        sm->hs1[(v * 5 + ul) * HS_STR + g] = make_float4(0.f, 0.f, 0.f, 0.f);
    }
    __syncthreads();

    const int bg = blockIdx.x * CTA + g * 4;
    const float* xg0 = g_xg + ((size_t)(bg + 0) * T_STEPS) * NGATE + v * 20;
    const float* xg1 = g_xg + ((size_t)(bg + 1) * T_STEPS) * NGATE + v * 20;
    const float* xg2 = g_xg + ((size_t)(bg + 2) * T_STEPS) * NGATE + v * 20;
    const float* xg3 = g_xg + ((size_t)(bg + 3) * T_STEPS) * NGATE + v * 20;

    const ulonglong2* w0h = reinterpret_cast<const ulonglong2*>(sm->w0h);
    const ulonglong2* w1x = reinterpret_cast<const ulonglong2*>(sm->w1x);
    const ulonglong2* w1h = reinterpret_cast<const ulonglong2*>(sm->w1h);
    const ulonglong2* bias1 = reinterpret_cast<const ulonglong2*>(sm->bias1) + v * 5;
    float4* hs0 = sm->hs0;
    float4* hs1 = sm->hs1;

    float c0[20], c1[20];
    #pragma unroll
    for (int i = 0; i < 20; i++) { c0[i] = 0.f; c1[i] = 0.f; }

    ull a[40];

    #pragma unroll 1
    for (int t = 0; t < T_STEPS; t++) {
        // ===== layer 0: acc = xg (bias folded in GEMM) =====
        {
            const float4* p0 = (const float4*)(xg0 + t * NGATE);
            const float4* p1 = (const float4*)(xg1 + t * NGATE);
            const float4* p2 = (const float4*)(xg2 + t * NGATE);
            const float4* p3 = (const float4*)(xg3 + t * NGATE);
            #pragma unroll
            for (int u = 0; u < 5; u++) {
                float4 q0 = p0[u], q1 = p1[u], q2 = p2[u], q3 = p3[u];
                a[      2*u] = packxy(q0.x, q0.y); a[      2*u+1] = packxy(q0.z, q0.w);
                a[10 +  2*u] = packxy(q1.x, q1.y); a[10 +  2*u+1] = packxy(q1.z, q1.w);
                a[20 +  2*u] = packxy(q2.x, q2.y); a[20 +  2*u+1] = packxy(q2.z, q2.w);
                a[30 +  2*u] = packxy(q3.x, q3.y); a[30 +  2*u+1] = packxy(q3.z, q3.w);
            }
        }
        #pragma unroll 4
        for (int k = 0; k < H; k++) {
            float4 hv = hs0[k * HS_STR + g];
            accum4(a, w0h + k * 20 + v * 5,
                   pack2(hv.x), pack2(hv.y), pack2(hv.z), pack2(hv.w));
        }
        #pragma unroll
        for (int ul = 0; ul < 5; ul++) {
            float hv[4];
            #pragma unroll
            for (int e = 0; e < 4; e++) {
                const ull* ae = a + e * 10;
                float iv = sig_ (getf(ae,      ul));
                float fv = sig_ (getf(ae,  5 + ul));
                float gv = tanh_(getf(ae, 10 + ul));
                float ov = sig_ (getf(ae, 15 + ul));
                float cn = fv * c0[e*5 + ul] + iv * gv;
                c0[e*5 + ul] = cn;
                hv[e] = ov * tanh_(cn);
            }
            hs0[(v * 5 + ul) * HS_STR + g] = make_float4(hv[0], hv[1], hv[2], hv[3]);
        }
        __syncwarp();

        // ===== layer 1 =====
        #pragma unroll
        for (int c = 0; c < 5; c++) {
            ulonglong2 bb = bias1[c];
            a[2*c] = bb.x; a[2*c+1] = bb.y;
            a[10+2*c] = bb.x; a[10+2*c+1] = bb.y;
            a[20+2*c] = bb.x; a[20+2*c+1] = bb.y;
            a[30+2*c] = bb.x; a[30+2*c+1] = bb.y;
        }
        #pragma unroll 4
        for (int k = 0; k < H; k++) {
            float4 hv = hs0[k * HS_STR + g];
            accum4(a, w1x + k * 20 + v * 5,
                   pack2(hv.x), pack2(hv.y), pack2(hv.z), pack2(hv.w));
        }
        #pragma unroll 4
        for (int k = 0; k < H; k++) {
            float4 hv = hs1[k * HS_STR + g];
            accum4(a, w1h + k * 20 + v * 5,
                   pack2(hv.x), pack2(hv.y), pack2(hv.z), pack2(hv.w));
        }
        #pragma unroll
        for (int ul = 0; ul < 5; ul++) {
            float hv[4];
            #pragma unroll
            for (int e = 0; e < 4; e++) {
                const ull* ae = a + e * 10;
                float iv = sig_ (getf(ae,      ul));
                float fv = sig_ (getf(ae,  5 + ul));
                float gv = tanh_(getf(ae, 10 + ul));
                float ov = sig_ (getf(ae, 15 + ul));
                float cn = fv * c1[e*5 + ul] + iv * gv;
                c1[e*5 + ul] = cn;
                hv[e] = ov * tanh_(cn);
            }
            hs1[(v * 5 + ul) * HS_STR + g] = make_float4(hv[0], hv[1], hv[2], hv[3]);
        }
        __syncwarp();
    }

    // ---- FC + softmax(2) ----
    float l0 = sm->bfc[0], l1 = sm->bfc[1];
    #pragma unroll
    for (int k = 0; k < H; k++) {
        float4 hq = hs1[k * HS_STR + g];
        float hk = (v == 0) ? hq.x : (v == 1) ? hq.y : (v == 2) ? hq.z : hq.w;
        l0 += sm->wfc[k]     * hk;
        l1 += sm->wfc[H + k] * hk;
    }
    float p0 = sig_(l0 - l1);
    reinterpret_cast<float2*>(out)[bg + v] = make_float2(p0, 1.0f - p0);
}

// ---------------- launch ----------------
extern "C" void kernel_launch(void* const* d_in, const int* in_sizes, int n_in,
                              void* d_out, int out_size) {
    const float* x    = (const float*)d_in[0];
    const float* Wih0 = (const float*)d_in[1];
    const float* Whh0 = (const float*)d_in[2];
    const float* bih0 = (const float*)d_in[3];
    const float* bhh0 = (const float*)d_in[4];
    const float* Wih1 = (const float*)d_in[5];
    const float* Whh1 = (const float*)d_in[6];
    const float* bih1 = (const float*)d_in[7];
    const float* bhh1 = (const float*)d_in[8];
    const float* Wfc  = (const float*)d_in[9];
    const float* bfc  = (const float*)d_in[10];
    float* out = (float*)d_out;

    cudaFuncSetAttribute(xg_gemm_kernel, cudaFuncAttributeMaxDynamicSharedMemorySize, G_SMEM);
    xg_gemm_kernel<<<G_GRID, G_CTA, G_SMEM>>>(x, Wih0, bih0, bhh0);

    const size_t smem2 = sizeof(SMR);
    cudaFuncSetAttribute(lstm2_rec_kernel, cudaFuncAttributeMaxDynamicSharedMemorySize, (int)smem2);
    lstm2_rec_kernel<<<B_TOTAL / CTA, CTA, smem2>>>(
        Whh0, Wih1, Whh1, bih1, bhh1, Wfc, bfc, out);
}

// round 9
// speedup vs baseline: 1.6229x; 1.1896x over previous
#include <cuda_runtime.h>
#include <cuda_bf16.h>
#include <cstdint>

typedef unsigned long long ull;

#define B_TOTAL 131072
#define T_STEPS 30
#define DIN     88
#define H       20
#define NGATE   80

// ================= GEMM (layer-0 input projection, HMMA, persistent) =================
#define M_ROWS   (B_TOTAL * T_STEPS)      // 3932160
#define M_TILE   128
#define N_TILES  (M_ROWS / M_TILE)        // 30720
#define G_GRID   296                      // 2 CTAs/SM persistent
#define G_CTA    128
#define AST      104                      // A smem row stride in bf16 (208 B)
#define BST      104
#define CST      84                       // C stage row stride in f32 (336 B, 16B-aligned)

// smem byte offsets
#define SO_AHI   512                      // 128 x 104 bf16 = 26624
#define SO_ALO   (SO_AHI + 26624)         // 27136
#define SO_BHI   (SO_ALO + 26624)         // 53760
#define SO_BLO   (SO_BHI + 16640)         // 70400
#define G_SMEM   (SO_BLO + 16640)         // 87040  (2 CTAs/SM = 174KB)
#define SO_CSTG  SO_AHI                   // C stage aliases A (dead after MMA sync); 128*336=43008 < 53248

// 1.26 GB scratch for xg[b*T + t][80] (rec-kernel gate order), fp32
__device__ float g_xg[(size_t)M_ROWS * NGATE];

// ---------------- helpers ----------------
__device__ __forceinline__ void split4(float4 f, ull& hi4, ull& lo4) {
    __nv_bfloat16 hx = __float2bfloat16_rn(f.x);
    __nv_bfloat16 hy = __float2bfloat16_rn(f.y);
    __nv_bfloat16 hz = __float2bfloat16_rn(f.z);
    __nv_bfloat16 hw = __float2bfloat16_rn(f.w);
    __nv_bfloat16 lx = __float2bfloat16_rn(f.x - __bfloat162float(hx));
    __nv_bfloat16 ly = __float2bfloat16_rn(f.y - __bfloat162float(hy));
    __nv_bfloat16 lz = __float2bfloat16_rn(f.z - __bfloat162float(hz));
    __nv_bfloat16 lw = __float2bfloat16_rn(f.w - __bfloat162float(hw));
    hi4 = (ull)__bfloat16_as_ushort(hx) | ((ull)__bfloat16_as_ushort(hy) << 16)
        | ((ull)__bfloat16_as_ushort(hz) << 32) | ((ull)__bfloat16_as_ushort(hw) << 48);
    lo4 = (ull)__bfloat16_as_ushort(lx) | ((ull)__bfloat16_as_ushort(ly) << 16)
        | ((ull)__bfloat16_as_ushort(lz) << 32) | ((ull)__bfloat16_as_ushort(lw) << 48);
}

__device__ __forceinline__ void mma16816(float* d,
                                         uint32_t a0, uint32_t a1, uint32_t a2, uint32_t a3,
                                         uint32_t b0, uint32_t b1) {
    asm volatile(
        "mma.sync.aligned.m16n8k16.row.col.f32.bf16.bf16.f32 "
        "{%0,%1,%2,%3}, {%4,%5,%6,%7}, {%8,%9}, {%0,%1,%2,%3};"
        : "+f"(d[0]), "+f"(d[1]), "+f"(d[2]), "+f"(d[3])
        : "r"(a0), "r"(a1), "r"(a2), "r"(a3), "r"(b0), "r"(b1));
}

// natural gate row n -> rec-layout position j (inverse of the rec permutation)
__device__ __forceinline__ int inv_perm(int n) {
    int g2 = n / 20, r = n % 20, v = r / 5, u = r % 5;
    return v * 20 + g2 * 5 + u;
}

// ---------------- persistent GEMM kernel ----------------
__global__ void __launch_bounds__(G_CTA, 2)
xg_gemm_kernel(const float* __restrict__ x, const float* __restrict__ Wih0,
               const float* __restrict__ bih0, const float* __restrict__ bhh0)
{
    extern __shared__ char smem[];
    const int tid = threadIdx.x;
    const int warp = tid >> 5, lane = tid & 31;
    const int gid = lane >> 2, tg = lane & 3;

    // ---- one-time: B hi/lo staging (natural gate-row order) ----
    if (tid < NGATE) {
        char* bhi = smem + SO_BHI + tid * (BST * 2);
        char* blo = smem + SO_BLO + tid * (BST * 2);
        const float4* wr = (const float4*)(Wih0 + tid * DIN);
        float4 wv[22];
        #pragma unroll
        for (int q = 0; q < 22; q++) wv[q] = wr[q];
        #pragma unroll
        for (int q = 0; q < 22; q++) {
            ull hi4, lo4;
            split4(wv[q], hi4, lo4);
            *(ull*)(bhi + q * 8) = hi4;
            *(ull*)(blo + q * 8) = lo4;
        }
        *(ull*)(bhi + 176) = 0; *(ull*)(bhi + 184) = 0;
        *(ull*)(blo + 176) = 0; *(ull*)(blo + 184) = 0;
    }

    // ---- per-thread constants: bias (natural col order) + inv-perm offsets ----
    float2 bias_r[10];
    int ipa[10], ipb[10];
    #pragma unroll
    for (int nf = 0; nf < 10; nf++) {
        int n0 = nf * 8 + tg * 2;
        bias_r[nf] = make_float2(bih0[n0] + bhh0[n0], bih0[n0 + 1] + bhh0[n0 + 1]);
        ipa[nf] = inv_perm(n0);
        ipb[nf] = inv_perm(n0 + 1);
    }

    // ---- coalesced prefetch of first tile (float4 index q*128+tid) ----
    int tile = blockIdx.x;
    float4 xr[22];
    if (tile < N_TILES) {
        const float4* xp = (const float4*)(x + (size_t)tile * M_TILE * DIN);
        #pragma unroll
        for (int q = 0; q < 22; q++) xr[q] = xp[q * 128 + tid];
    }
    __syncthreads();

    #pragma unroll 1
    for (; tile < N_TILES; tile += G_GRID) {
        // ---- phase 1: split + scatter-store A (regs hold coalesced chunks) ----
        #pragma unroll
        for (int q = 0; q < 22; q++) {
            int e = q * 512 + tid * 4;          // element index within 128x88 tile
            int r = e / 88;
            int cc = e - r * 88;
            int addr = r * (AST * 2) + cc * 2;  // bytes
            ull hi4, lo4;
            split4(xr[q], hi4, lo4);
            *(ull*)(smem + SO_AHI + addr) = hi4;
            *(ull*)(smem + SO_ALO + addr) = lo4;
        }
        // re-zero pads (cstg alias clobbers them): thread tid owns row tid
        {
            char* ah = smem + SO_AHI + tid * (AST * 2);
            char* al = smem + SO_ALO + tid * (AST * 2);
            *(ull*)(ah + 176) = 0; *(ull*)(ah + 184) = 0;
            *(ull*)(al + 176) = 0; *(ull*)(al + 184) = 0;
        }
        __syncthreads();

        // ---- phase 2: coalesced prefetch of next tile (overlaps MMA) ----
        {
            int nxt = tile + G_GRID;
            if (nxt < N_TILES) {
                const float4* xp = (const float4*)(x + (size_t)nxt * M_TILE * DIN);
                #pragma unroll
                for (int q = 0; q < 22; q++) xr[q] = xp[q * 128 + tid];
            }
        }

        // ---- MMA mainloop: 18 k16 steps, 3 bf16-split segments ----
        float c[2][10][4];
        #pragma unroll
        for (int mf = 0; mf < 2; mf++)
            #pragma unroll
            for (int nf = 0; nf < 10; nf++)
                #pragma unroll
                for (int q = 0; q < 4; q++) c[mf][nf][q] = 0.f;

        #pragma unroll 1
        for (int s = 0; s < 18; s++) {
            const char* As = smem + ((s < 12) ? SO_AHI : SO_ALO);
            const char* Bs = smem + ((s < 6) ? SO_BHI : (s < 12 ? SO_BLO : SO_BHI));
            const int ko = (s % 6) * 16;

            uint32_t bf[10][2];
            #pragma unroll
            for (int nf = 0; nf < 10; nf++) {
                int n = nf * 8 + gid;
                const char* bp = Bs + n * (BST * 2) + (ko + tg * 2) * 2;
                bf[nf][0] = *(const uint32_t*)(bp);
                bf[nf][1] = *(const uint32_t*)(bp + 16);
            }
            #pragma unroll
            for (int mf = 0; mf < 2; mf++) {
                int m = warp * 32 + mf * 16 + gid;
                const char* ap0 = As + m * (AST * 2) + (ko + tg * 2) * 2;
                const char* ap1 = ap0 + 8 * (AST * 2);
                uint32_t a0 = *(const uint32_t*)(ap0);
                uint32_t a1 = *(const uint32_t*)(ap1);
                uint32_t a2 = *(const uint32_t*)(ap0 + 16);
                uint32_t a3 = *(const uint32_t*)(ap1 + 16);
                #pragma unroll
                for (int nf = 0; nf < 10; nf++)
                    mma16816(c[mf][nf], a0, a1, a2, a3, bf[nf][0], bf[nf][1]);
            }
        }
        __syncthreads();   // all warps done reading A -> safe to alias as C stage

        // ---- epilogue: frags -> cstg PERMUTED + bias, then coalesced stream-out ----
        float* cw = (float*)(smem + SO_CSTG + warp * (32 * CST * 4));
        #pragma unroll
        for (int mf = 0; mf < 2; mf++) {
            int row0 = mf * 16 + gid;
            #pragma unroll
            for (int nf = 0; nf < 10; nf++) {
                float bx = bias_r[nf].x, by = bias_r[nf].y;
                cw[ row0      * CST + ipa[nf]] = c[mf][nf][0] + bx;
                cw[ row0      * CST + ipb[nf]] = c[mf][nf][1] + by;
                cw[(row0 + 8) * CST + ipa[nf]] = c[mf][nf][2] + bx;
                cw[(row0 + 8) * CST + ipb[nf]] = c[mf][nf][3] + by;
            }
        }
        __syncwarp();
        {
            // warp's 32 rows x 80 f32 = contiguous 10240B in g_xg
            float4* dstw = (float4*)(g_xg + ((size_t)tile * M_TILE + warp * 32) * NGATE);
            #pragma unroll
            for (int i = 0; i < 20; i++) {
                int k = i * 32 + lane;          // float4 chunk within warp region
                int row = k / 20;
                int c4 = k - row * 20;
                float4 v4 = *(const float4*)(cw + row * CST + c4 * 4);
                dstw[k] = v4;
            }
        }
        __syncthreads();   // cstg reads done before next tile's A scatter-store
    }
}

// ================= recurrent kernel (EXACT R8 version, 1014us measured) =================
#define CTA     128
#define HS_STR  33

struct __align__(16) SMR {
    float w0h[H * 80];
    float w1x[H * 80];
    float w1h[H * 80];
    float bias1[80];
    float wfc[2 * H];
    float bfc[2];
    float4 hs0[H * HS_STR];
    float4 hs1[H * HS_STR];
};

__device__ __forceinline__ ull ffma2(ull a, ull b, ull c) {
    ull d;
    asm("fma.rn.f32x2 %0, %1, %2, %3;" : "=l"(d) : "l"(a), "l"(b), "l"(c));
    return d;
}
__device__ __forceinline__ ull pack2(float x) {
    ull r;
    asm("mov.b64 %0, {%1, %1};" : "=l"(r) : "f"(x));
    return r;
}
__device__ __forceinline__ ull packxy(float x, float y) {
    ull r;
    asm("mov.b64 %0, {%1, %2};" : "=l"(r) : "f"(x), "f"(y));
    return r;
}
__device__ __forceinline__ float getf(const ull* acc, int idx) {
    ull v = acc[idx >> 1];
    unsigned u = (idx & 1) ? (unsigned)(v >> 32) : (unsigned)(v & 0xffffffffu);
    return __uint_as_float(u);
}
__device__ __forceinline__ float sig_(float x) {
    return __fdividef(1.0f, 1.0f + __expf(-x));
}
__device__ __forceinline__ float tanh_(float x) {
    float a = fabsf(x);
    float e = __expf(a + a);
    float r = 1.0f - __fdividef(2.0f, e + 1.0f);
    return copysignf(r, x);
}
__device__ __forceinline__ void accum4(ull* a, const ulonglong2* __restrict__ w,
                                       ull x0, ull x1, ull x2, ull x3) {
    #pragma unroll
    for (int c = 0; c < 5; c++) {
        ulonglong2 wc = w[c];
        a[ 0 + 2*c]   = ffma2(wc.x, x0, a[ 0 + 2*c]);
        a[ 0 + 2*c+1] = ffma2(wc.y, x0, a[ 0 + 2*c+1]);
        a[10 + 2*c]   = ffma2(wc.x, x1, a[10 + 2*c]);
        a[10 + 2*c+1] = ffma2(wc.y, x1, a[10 + 2*c+1]);
        a[20 + 2*c]   = ffma2(wc.x, x2, a[20 + 2*c]);
        a[20 + 2*c+1] = ffma2(wc.y, x2, a[20 + 2*c+1]);
        a[30 + 2*c]   = ffma2(wc.x, x3, a[30 + 2*c]);
        a[30 + 2*c+1] = ffma2(wc.y, x3, a[30 + 2*c+1]);
    }
}

__global__ void __launch_bounds__(CTA, 3) lstm2_rec_kernel(
    const float* __restrict__ Whh0,
    const float* __restrict__ Wih1, const float* __restrict__ Whh1,
    const float* __restrict__ bih1, const float* __restrict__ bhh1,
    const float* __restrict__ Wfc,  const float* __restrict__ bfc,
    float* __restrict__ out)
{
    extern __shared__ unsigned char smraw[];
    SMR* sm = reinterpret_cast<SMR*>(smraw);
    const int tid = threadIdx.x;

    #pragma unroll 1
    for (int idx = tid; idx < H * 80; idx += CTA) {
        int d = idx / 80, rem = idx - d * 80;
        int v = rem / 20, o = rem - v * 20;
        int row = (o / 5) * 20 + v * 5 + (o % 5);
        sm->w0h[idx] = Whh0[row * H + d];
        sm->w1x[idx] = Wih1[row * H + d];
        sm->w1h[idx] = Whh1[row * H + d];
    }
    if (tid < 80) {
        int v = tid / 20, o = tid - v * 20;
        int row = (o / 5) * 20 + v * 5 + (o % 5);
        sm->bias1[tid] = bih1[row] + bhh1[row];
    }
    if (tid < 2 * H) sm->wfc[tid] = Wfc[tid];
    if (tid < 2)     sm->bfc[tid] = bfc[tid];

    const int g = tid >> 2;
    const int v = tid & 3;

    #pragma unroll
    for (int ul = 0; ul < 5; ul++) {
        sm->hs0[(v * 5 + ul) * HS_STR + g] = make_float4(0.f, 0.f, 0.f, 0.f);
        sm->hs1[(v * 5 + ul) * HS_STR + g] = make_float4(0.f, 0.f, 0.f, 0.f);
    }
    __syncthreads();

    const int bg = blockIdx.x * CTA + g * 4;
    const float* xg0 = g_xg + ((size_t)(bg + 0) * T_STEPS) * NGATE + v * 20;
    const float* xg1 = g_xg + ((size_t)(bg + 1) * T_STEPS) * NGATE + v * 20;
    const float* xg2 = g_xg + ((size_t)(bg + 2) * T_STEPS) * NGATE + v * 20;
    const float* xg3 = g_xg + ((size_t)(bg + 3) * T_STEPS) * NGATE + v * 20;

    const ulonglong2* w0h = reinterpret_cast<const ulonglong2*>(sm->w0h);
    const ulonglong2* w1x = reinterpret_cast<const ulonglong2*>(sm->w1x);
    const ulonglong2* w1h = reinterpret_cast<const ulonglong2*>(sm->w1h);
    const ulonglong2* bias1 = reinterpret_cast<const ulonglong2*>(sm->bias1) + v * 5;
    float4* hs0 = sm->hs0;
    float4* hs1 = sm->hs1;

    float c0[20], c1[20];
    #pragma unroll
    for (int i = 0; i < 20; i++) { c0[i] = 0.f; c1[i] = 0.f; }

    ull a[40];

    #pragma unroll 1
    for (int t = 0; t < T_STEPS; t++) {
        // ===== layer 0: acc = xg (bias folded in GEMM) =====
        {
            const float4* p0 = (const float4*)(xg0 + t * NGATE);
            const float4* p1 = (const float4*)(xg1 + t * NGATE);
            const float4* p2 = (const float4*)(xg2 + t * NGATE);
            const float4* p3 = (const float4*)(xg3 + t * NGATE);
            #pragma unroll
            for (int u = 0; u < 5; u++) {
                float4 q0 = p0[u], q1 = p1[u], q2 = p2[u], q3 = p3[u];
                a[      2*u] = packxy(q0.x, q0.y); a[      2*u+1] = packxy(q0.z, q0.w);
                a[10 +  2*u] = packxy(q1.x, q1.y); a[10 +  2*u+1] = packxy(q1.z, q1.w);
                a[20 +  2*u] = packxy(q2.x, q2.y); a[20 +  2*u+1] = packxy(q2.z, q2.w);
                a[30 +  2*u] = packxy(q3.x, q3.y); a[30 +  2*u+1] = packxy(q3.z, q3.w);
            }
        }
        #pragma unroll 4
        for (int k = 0; k < H; k++) {
            float4 hv = hs0[k * HS_STR + g];
            accum4(a, w0h + k * 20 + v * 5,
                   pack2(hv.x), pack2(hv.y), pack2(hv.z), pack2(hv.w));
        }
        #pragma unroll
        for (int ul = 0; ul < 5; ul++) {
            float hv[4];
            #pragma unroll
            for (int e = 0; e < 4; e++) {
                const ull* ae = a + e * 10;
                float iv = sig_ (getf(ae,      ul));
                float fv = sig_ (getf(ae,  5 + ul));
                float gv = tanh_(getf(ae, 10 + ul));
                float ov = sig_ (getf(ae, 15 + ul));
                float cn = fv * c0[e*5 + ul] + iv * gv;
                c0[e*5 + ul] = cn;
                hv[e] = ov * tanh_(cn);
            }
            hs0[(v * 5 + ul) * HS_STR + g] = make_float4(hv[0], hv[1], hv[2], hv[3]);
        }
        __syncwarp();

        // ===== layer 1 =====
        #pragma unroll
        for (int c = 0; c < 5; c++) {
            ulonglong2 bb = bias1[c];
            a[2*c] = bb.x; a[2*c+1] = bb.y;
            a[10+2*c] = bb.x; a[10+2*c+1] = bb.y;
            a[20+2*c] = bb.x; a[20+2*c+1] = bb.y;
            a[30+2*c] = bb.x; a[30+2*c+1] = bb.y;
        }
        #pragma unroll 4
        for (int k = 0; k < H; k++) {
            float4 hv = hs0[k * HS_STR + g];
            accum4(a, w1x + k * 20 + v * 5,
                   pack2(hv.x), pack2(hv.y), pack2(hv.z), pack2(hv.w));
        }
        #pragma unroll 4
        for (int k = 0; k < H; k++) {
            float4 hv = hs1[k * HS_STR + g];
            accum4(a, w1h + k * 20 + v * 5,
                   pack2(hv.x), pack2(hv.y), pack2(hv.z), pack2(hv.w));
        }
        #pragma unroll
        for (int ul = 0; ul < 5; ul++) {
            float hv[4];
            #pragma unroll
            for (int e = 0; e < 4; e++) {
                const ull* ae = a + e * 10;
                float iv = sig_ (getf(ae,      ul));
                float fv = sig_ (getf(ae,  5 + ul));
                float gv = tanh_(getf(ae, 10 + ul));
                float ov = sig_ (getf(ae, 15 + ul));
                float cn = fv * c1[e*5 + ul] + iv * gv;
                c1[e*5 + ul] = cn;
                hv[e] = ov * tanh_(cn);
            }
            hs1[(v * 5 + ul) * HS_STR + g] = make_float4(hv[0], hv[1], hv[2], hv[3]);
        }
        __syncwarp();
    }

    // ---- FC + softmax(2) ----
    float l0 = sm->bfc[0], l1 = sm->bfc[1];
    #pragma unroll
    for (int k = 0; k < H; k++) {
        float4 hq = hs1[k * HS_STR + g];
        float hk = (v == 0) ? hq.x : (v == 1) ? hq.y : (v == 2) ? hq.z : hq.w;
        l0 += sm->wfc[k]     * hk;
        l1 += sm->wfc[H + k] * hk;
    }
    float p0 = sig_(l0 - l1);
    reinterpret_cast<float2*>(out)[bg + v] = make_float2(p0, 1.0f - p0);
}

// ---------------- launch ----------------
extern "C" void kernel_launch(void* const* d_in, const int* in_sizes, int n_in,
                              void* d_out, int out_size) {
    const float* x    = (const float*)d_in[0];
    const float* Wih0 = (const float*)d_in[1];
    const float* Whh0 = (const float*)d_in[2];
    const float* bih0 = (const float*)d_in[3];
    const float* bhh0 = (const float*)d_in[4];
    const float* Wih1 = (const float*)d_in[5];
    const float* Whh1 = (const float*)d_in[6];
    const float* bih1 = (const float*)d_in[7];
    const float* bhh1 = (const float*)d_in[8];
    const float* Wfc  = (const float*)d_in[9];
    const float* bfc  = (const float*)d_in[10];
    float* out = (float*)d_out;

    cudaFuncSetAttribute(xg_gemm_kernel, cudaFuncAttributeMaxDynamicSharedMemorySize, G_SMEM);
    xg_gemm_kernel<<<G_GRID, G_CTA, G_SMEM>>>(x, Wih0, bih0, bhh0);

    const size_t smem2 = sizeof(SMR);
    cudaFuncSetAttribute(lstm2_rec_kernel, cudaFuncAttributeMaxDynamicSharedMemorySize, (int)smem2);
    lstm2_rec_kernel<<<B_TOTAL / CTA, CTA, smem2>>>(
        Whh0, Wih1, Whh1, bih1, bhh1, Wfc, bfc, out);
}

// round 10
// speedup vs baseline: 1.7492x; 1.0778x over previous
#include <cuda_runtime.h>
#include <cuda_bf16.h>
#include <cstdint>

typedef unsigned long long ull;

#define B_TOTAL 131072
#define T_STEPS 30
#define DIN     88
#define H       20
#define NGATE   80

// ================= GEMM (layer-0 input projection, HMMA, persistent) =================
#define M_ROWS   (B_TOTAL * T_STEPS)      // 3932160
#define M_TILE   128
#define N_TILES  (M_ROWS / M_TILE)        // 30720
#define G_GRID   296                      // 2 CTAs/SM persistent
#define G_CTA    128
#define AST      104                      // A smem row stride in bf16 (208 B)
#define BST      104
#define CST      84                       // C stage row stride in f32 (336 B, 16B-aligned)

// smem byte offsets
#define SO_AHI   512                      // 128 x 104 bf16 = 26624
#define SO_ALO   (SO_AHI + 26624)         // 27136
#define SO_BHI   (SO_ALO + 26624)         // 53760
#define SO_BLO   (SO_BHI + 16640)         // 70400
#define G_SMEM   (SO_BLO + 16640)         // 87040  (2 CTAs/SM = 174KB)
#define SO_CSTG  SO_AHI                   // C stage aliases A (dead after MMA sync); 128*336=43008 < 53248

// 1.26 GB scratch for xg[b*T + t][80] (rec-kernel gate order), fp32
__device__ float g_xg[(size_t)M_ROWS * NGATE];

// ---------------- helpers ----------------
__device__ __forceinline__ void split4(float4 f, ull& hi4, ull& lo4) {
    __nv_bfloat16 hx = __float2bfloat16_rn(f.x);
    __nv_bfloat16 hy = __float2bfloat16_rn(f.y);
    __nv_bfloat16 hz = __float2bfloat16_rn(f.z);
    __nv_bfloat16 hw = __float2bfloat16_rn(f.w);
    __nv_bfloat16 lx = __float2bfloat16_rn(f.x - __bfloat162float(hx));
    __nv_bfloat16 ly = __float2bfloat16_rn(f.y - __bfloat162float(hy));
    __nv_bfloat16 lz = __float2bfloat16_rn(f.z - __bfloat162float(hz));
    __nv_bfloat16 lw = __float2bfloat16_rn(f.w - __bfloat162float(hw));
    hi4 = (ull)__bfloat16_as_ushort(hx) | ((ull)__bfloat16_as_ushort(hy) << 16)
        | ((ull)__bfloat16_as_ushort(hz) << 32) | ((ull)__bfloat16_as_ushort(hw) << 48);
    lo4 = (ull)__bfloat16_as_ushort(lx) | ((ull)__bfloat16_as_ushort(ly) << 16)
        | ((ull)__bfloat16_as_ushort(lz) << 32) | ((ull)__bfloat16_as_ushort(lw) << 48);
}

__device__ __forceinline__ void mma16816(float* d,
                                         uint32_t a0, uint32_t a1, uint32_t a2, uint32_t a3,
                                         uint32_t b0, uint32_t b1) {
    asm volatile(
        "mma.sync.aligned.m16n8k16.row.col.f32.bf16.bf16.f32 "
        "{%0,%1,%2,%3}, {%4,%5,%6,%7}, {%8,%9}, {%0,%1,%2,%3};"
        : "+f"(d[0]), "+f"(d[1]), "+f"(d[2]), "+f"(d[3])
        : "r"(a0), "r"(a1), "r"(a2), "r"(a3), "r"(b0), "r"(b1));
}

// natural gate row n -> rec-layout position j (inverse of the rec permutation)
__device__ __forceinline__ int inv_perm(int n) {
    int g2 = n / 20, r = n % 20, v = r / 5, u = r % 5;
    return v * 20 + g2 * 5 + u;
}

// ---------------- persistent GEMM kernel ----------------
__global__ void __launch_bounds__(G_CTA, 2)
xg_gemm_kernel(const float* __restrict__ x, const float* __restrict__ Wih0,
               const float* __restrict__ bih0, const float* __restrict__ bhh0)
{
    extern __shared__ char smem[];
    const int tid = threadIdx.x;
    const int warp = tid >> 5, lane = tid & 31;
    const int gid = lane >> 2, tg = lane & 3;

    // ---- one-time: B hi/lo staging (natural gate-row order) ----
    if (tid < NGATE) {
        char* bhi = smem + SO_BHI + tid * (BST * 2);
        char* blo = smem + SO_BLO + tid * (BST * 2);
        const float4* wr = (const float4*)(Wih0 + tid * DIN);
        float4 wv[22];
        #pragma unroll
        for (int q = 0; q < 22; q++) wv[q] = wr[q];
        #pragma unroll
        for (int q = 0; q < 22; q++) {
            ull hi4, lo4;
            split4(wv[q], hi4, lo4);
            *(ull*)(bhi + q * 8) = hi4;
            *(ull*)(blo + q * 8) = lo4;
        }
        *(ull*)(bhi + 176) = 0; *(ull*)(bhi + 184) = 0;
        *(ull*)(blo + 176) = 0; *(ull*)(blo + 184) = 0;
    }

    // ---- per-thread constants: bias (natural col order) + inv-perm offsets ----
    float2 bias_r[10];
    int ipa[10], ipb[10];
    #pragma unroll
    for (int nf = 0; nf < 10; nf++) {
        int n0 = nf * 8 + tg * 2;
        bias_r[nf] = make_float2(bih0[n0] + bhh0[n0], bih0[n0 + 1] + bhh0[n0 + 1]);
        ipa[nf] = inv_perm(n0);
        ipb[nf] = inv_perm(n0 + 1);
    }

    // ---- coalesced prefetch of first tile (float4 index q*128+tid) ----
    int tile = blockIdx.x;
    float4 xr[22];
    if (tile < N_TILES) {
        const float4* xp = (const float4*)(x + (size_t)tile * M_TILE * DIN);
        #pragma unroll
        for (int q = 0; q < 22; q++) xr[q] = xp[q * 128 + tid];
    }
    __syncthreads();

    #pragma unroll 1
    for (; tile < N_TILES; tile += G_GRID) {
        // ---- phase 1: split + scatter-store A (regs hold coalesced chunks) ----
        #pragma unroll
        for (int q = 0; q < 22; q++) {
            int e = q * 512 + tid * 4;          // element index within 128x88 tile
            int r = e / 88;
            int cc = e - r * 88;
            int addr = r * (AST * 2) + cc * 2;  // bytes
            ull hi4, lo4;
            split4(xr[q], hi4, lo4);
            *(ull*)(smem + SO_AHI + addr) = hi4;
            *(ull*)(smem + SO_ALO + addr) = lo4;
        }
        // re-zero pads (cstg alias clobbers them): thread tid owns row tid
        {
            char* ah = smem + SO_AHI + tid * (AST * 2);
            char* al = smem + SO_ALO + tid * (AST * 2);
            *(ull*)(ah + 176) = 0; *(ull*)(ah + 184) = 0;
            *(ull*)(al + 176) = 0; *(ull*)(al + 184) = 0;
        }
        __syncthreads();

        // ---- phase 2: coalesced prefetch of next tile (overlaps MMA) ----
        {
            int nxt = tile + G_GRID;
            if (nxt < N_TILES) {
                const float4* xp = (const float4*)(x + (size_t)nxt * M_TILE * DIN);
                #pragma unroll
                for (int q = 0; q < 22; q++) xr[q] = xp[q * 128 + tid];
            }
        }

        // ---- MMA mainloop: 6 ko steps, each fragment loaded ONCE ----
        // acc += a_hi*b_hi + a_hi*b_lo + a_lo*b_hi
        float c[2][10][4];
        #pragma unroll
        for (int mf = 0; mf < 2; mf++)
            #pragma unroll
            for (int nf = 0; nf < 10; nf++)
                #pragma unroll
                for (int q = 0; q < 4; q++) c[mf][nf][q] = 0.f;

        #pragma unroll 1
        for (int ko6 = 0; ko6 < 6; ko6++) {
            const int kb = (ko6 * 16 + tg * 2) * 2;   // byte offset of this lane's k-pair

            uint32_t bh[10][2], bl[10][2];
            #pragma unroll
            for (int nf = 0; nf < 10; nf++) {
                int n = nf * 8 + gid;
                const char* bph = smem + SO_BHI + n * (BST * 2) + kb;
                const char* bpl = smem + SO_BLO + n * (BST * 2) + kb;
                bh[nf][0] = *(const uint32_t*)(bph);
                bh[nf][1] = *(const uint32_t*)(bph + 16);
                bl[nf][0] = *(const uint32_t*)(bpl);
                bl[nf][1] = *(const uint32_t*)(bpl + 16);
            }
            #pragma unroll
            for (int mf = 0; mf < 2; mf++) {
                int m = warp * 32 + mf * 16 + gid;
                const char* aph0 = smem + SO_AHI + m * (AST * 2) + kb;
                const char* aph1 = aph0 + 8 * (AST * 2);
                uint32_t ah0 = *(const uint32_t*)(aph0);
                uint32_t ah1 = *(const uint32_t*)(aph1);
                uint32_t ah2 = *(const uint32_t*)(aph0 + 16);
                uint32_t ah3 = *(const uint32_t*)(aph1 + 16);
                const char* apl0 = smem + SO_ALO + m * (AST * 2) + kb;
                const char* apl1 = apl0 + 8 * (AST * 2);
                uint32_t al0 = *(const uint32_t*)(apl0);
                uint32_t al1 = *(const uint32_t*)(apl1);
                uint32_t al2 = *(const uint32_t*)(apl0 + 16);
                uint32_t al3 = *(const uint32_t*)(apl1 + 16);
                #pragma unroll
                for (int nf = 0; nf < 10; nf++) {
                    mma16816(c[mf][nf], ah0, ah1, ah2, ah3, bh[nf][0], bh[nf][1]);
                    mma16816(c[mf][nf], ah0, ah1, ah2, ah3, bl[nf][0], bl[nf][1]);
                    mma16816(c[mf][nf], al0, al1, al2, al3, bh[nf][0], bh[nf][1]);
                }
            }
        }
        __syncthreads();   // all warps done reading A -> safe to alias as C stage

        // ---- epilogue: frags -> cstg PERMUTED + bias, then coalesced stream-out ----
        float* cw = (float*)(smem + SO_CSTG + warp * (32 * CST * 4));
        #pragma unroll
        for (int mf = 0; mf < 2; mf++) {
            int row0 = mf * 16 + gid;
            #pragma unroll
            for (int nf = 0; nf < 10; nf++) {
                float bx = bias_r[nf].x, by = bias_r[nf].y;
                cw[ row0      * CST + ipa[nf]] = c[mf][nf][0] + bx;
                cw[ row0      * CST + ipb[nf]] = c[mf][nf][1] + by;
                cw[(row0 + 8) * CST + ipa[nf]] = c[mf][nf][2] + bx;
                cw[(row0 + 8) * CST + ipb[nf]] = c[mf][nf][3] + by;
            }
        }
        __syncwarp();
        {
            // warp's 32 rows x 80 f32 = contiguous 10240B in g_xg
            float4* dstw = (float4*)(g_xg + ((size_t)tile * M_TILE + warp * 32) * NGATE);
            #pragma unroll
            for (int i = 0; i < 20; i++) {
                int k = i * 32 + lane;          // float4 chunk within warp region
                int row = k / 20;
                int c4 = k - row * 20;
                float4 v4 = *(const float4*)(cw + row * CST + c4 * 4);
                dstw[k] = v4;
            }
        }
        __syncthreads();   // cstg reads done before next tile's A scatter-store
    }
}

// ================= recurrent kernel (EXACT R9 version, 1012us measured) =================
#define CTA     128
#define HS_STR  33

struct __align__(16) SMR {
    float w0h[H * 80];
    float w1x[H * 80];
    float w1h[H * 80];
    float bias1[80];
    float wfc[2 * H];
    float bfc[2];
    float4 hs0[H * HS_STR];
    float4 hs1[H * HS_STR];
};

__device__ __forceinline__ ull ffma2(ull a, ull b, ull c) {
    ull d;
    asm("fma.rn.f32x2 %0, %1, %2, %3;" : "=l"(d) : "l"(a), "l"(b), "l"(c));
    return d;
}
__device__ __forceinline__ ull pack2(float x) {
    ull r;
    asm("mov.b64 %0, {%1, %1};" : "=l"(r) : "f"(x));
    return r;
}
__device__ __forceinline__ ull packxy(float x, float y) {
    ull r;
    asm("mov.b64 %0, {%1, %2};" : "=l"(r) : "f"(x), "f"(y));
    return r;
}
__device__ __forceinline__ float getf(const ull* acc, int idx) {
    ull v = acc[idx >> 1];
    unsigned u = (idx & 1) ? (unsigned)(v >> 32) : (unsigned)(v & 0xffffffffu);
    return __uint_as_float(u);
}
__device__ __forceinline__ float sig_(float x) {
    return __fdividef(1.0f, 1.0f + __expf(-x));
}
__device__ __forceinline__ float tanh_(float x) {
    float a = fabsf(x);
    float e = __expf(a + a);
    float r = 1.0f - __fdividef(2.0f, e + 1.0f);
    return copysignf(r, x);
}
__device__ __forceinline__ void accum4(ull* a, const ulonglong2* __restrict__ w,
                                       ull x0, ull x1, ull x2, ull x3) {
    #pragma unroll
    for (int c = 0; c < 5; c++) {
        ulonglong2 wc = w[c];
        a[ 0 + 2*c]   = ffma2(wc.x, x0, a[ 0 + 2*c]);
        a[ 0 + 2*c+1] = ffma2(wc.y, x0, a[ 0 + 2*c+1]);
        a[10 + 2*c]   = ffma2(wc.x, x1, a[10 + 2*c]);
        a[10 + 2*c+1] = ffma2(wc.y, x1, a[10 + 2*c+1]);
        a[20 + 2*c]   = ffma2(wc.x, x2, a[20 + 2*c]);
        a[20 + 2*c+1] = ffma2(wc.y, x2, a[20 + 2*c+1]);
        a[30 + 2*c]   = ffma2(wc.x, x3, a[30 + 2*c]);
        a[30 + 2*c+1] = ffma2(wc.y, x3, a[30 + 2*c+1]);
    }
}

__global__ void __launch_bounds__(CTA, 3) lstm2_rec_kernel(
    const float* __restrict__ Whh0,
    const float* __restrict__ Wih1, const float* __restrict__ Whh1,
    const float* __restrict__ bih1, const float* __restrict__ bhh1,
    const float* __restrict__ Wfc,  const float* __restrict__ bfc,
    float* __restrict__ out)
{
    extern __shared__ unsigned char smraw[];
    SMR* sm = reinterpret_cast<SMR*>(smraw);
    const int tid = threadIdx.x;

    #pragma unroll 1
    for (int idx = tid; idx < H * 80; idx += CTA) {
        int d = idx / 80, rem = idx - d * 80;
        int v = rem / 20, o = rem - v * 20;
        int row = (o / 5) * 20 + v * 5 + (o % 5);
        sm->w0h[idx] = Whh0[row * H + d];
        sm->w1x[idx] = Wih1[row * H + d];
        sm->w1h[idx] = Whh1[row * H + d];
    }
    if (tid < 80) {
        int v = tid / 20, o = tid - v * 20;
        int row = (o / 5) * 20 + v * 5 + (o % 5);
        sm->bias1[tid] = bih1[row] + bhh1[row];
    }
    if (tid < 2 * H) sm->wfc[tid] = Wfc[tid];
    if (tid < 2)     sm->bfc[tid] = bfc[tid];

    const int g = tid >> 2;
    const int v = tid & 3;

    #pragma unroll
    for (int ul = 0; ul < 5; ul++) {
        sm->hs0[(v * 5 + ul) * HS_STR + g] = make_float4(0.f, 0.f, 0.f, 0.f);
        sm->hs1[(v * 5 + ul) * HS_STR + g] = make_float4(0.f, 0.f, 0.f, 0.f);
    }
    __syncthreads();

    const int bg = blockIdx.x * CTA + g * 4;
    const float* xg0 = g_xg + ((size_t)(bg + 0) * T_STEPS) * NGATE + v * 20;
    const float* xg1 = g_xg + ((size_t)(bg + 1) * T_STEPS) * NGATE + v * 20;
    const float* xg2 = g_xg + ((size_t)(bg + 2) * T_STEPS) * NGATE + v * 20;
    const float* xg3 = g_xg + ((size_t)(bg + 3) * T_STEPS) * NGATE + v * 20;

    const ulonglong2* w0h = reinterpret_cast<const ulonglong2*>(sm->w0h);
    const ulonglong2* w1x = reinterpret_cast<const ulonglong2*>(sm->w1x);
    const ulonglong2* w1h = reinterpret_cast<const ulonglong2*>(sm->w1h);
    const ulonglong2* bias1 = reinterpret_cast<const ulonglong2*>(sm->bias1) + v * 5;
    float4* hs0 = sm->hs0;
    float4* hs1 = sm->hs1;

    float c0[20], c1[20];
    #pragma unroll
    for (int i = 0; i < 20; i++) { c0[i] = 0.f; c1[i] = 0.f; }

    ull a[40];

    #pragma unroll 1
    for (int t = 0; t < T_STEPS; t++) {
        // ===== layer 0: acc = xg (bias folded in GEMM) =====
        {
            const float4* p0 = (const float4*)(xg0 + t * NGATE);
            const float4* p1 = (const float4*)(xg1 + t * NGATE);
            const float4* p2 = (const float4*)(xg2 + t * NGATE);
            const float4* p3 = (const float4*)(xg3 + t * NGATE);
            #pragma unroll
            for (int u = 0; u < 5; u++) {
                float4 q0 = p0[u], q1 = p1[u], q2 = p2[u], q3 = p3[u];
                a[      2*u] = packxy(q0.x, q0.y); a[      2*u+1] = packxy(q0.z, q0.w);
                a[10 +  2*u] = packxy(q1.x, q1.y); a[10 +  2*u+1] = packxy(q1.z, q1.w);
                a[20 +  2*u] = packxy(q2.x, q2.y); a[20 +  2*u+1] = packxy(q2.z, q2.w);
                a[30 +  2*u] = packxy(q3.x, q3.y); a[30 +  2*u+1] = packxy(q3.z, q3.w);
            }
        }
        #pragma unroll 4
        for (int k = 0; k < H; k++) {
            float4 hv = hs0[k * HS_STR + g];
            accum4(a, w0h + k * 20 + v * 5,
                   pack2(hv.x), pack2(hv.y), pack2(hv.z), pack2(hv.w));
        }
        #pragma unroll
        for (int ul = 0; ul < 5; ul++) {
            float hv[4];
            #pragma unroll
            for (int e = 0; e < 4; e++) {
                const ull* ae = a + e * 10;
                float iv = sig_ (getf(ae,      ul));
                float fv = sig_ (getf(ae,  5 + ul));
                float gv = tanh_(getf(ae, 10 + ul));
                float ov = sig_ (getf(ae, 15 + ul));
                float cn = fv * c0[e*5 + ul] + iv * gv;
                c0[e*5 + ul] = cn;
                hv[e] = ov * tanh_(cn);
            }
            hs0[(v * 5 + ul) * HS_STR + g] = make_float4(hv[0], hv[1], hv[2], hv[3]);
        }
        __syncwarp();

        // ===== layer 1 =====
        #pragma unroll
        for (int c = 0; c < 5; c++) {
            ulonglong2 bb = bias1[c];
            a[2*c] = bb.x; a[2*c+1] = bb.y;
            a[10+2*c] = bb.x; a[10+2*c+1] = bb.y;
            a[20+2*c] = bb.x; a[20+2*c+1] = bb.y;
            a[30+2*c] = bb.x; a[30+2*c+1] = bb.y;
        }
        #pragma unroll 4
        for (int k = 0; k < H; k++) {
            float4 hv = hs0[k * HS_STR + g];
            accum4(a, w1x + k * 20 + v * 5,
                   pack2(hv.x), pack2(hv.y), pack2(hv.z), pack2(hv.w));
        }
        #pragma unroll 4
        for (int k = 0; k < H; k++) {
            float4 hv = hs1[k * HS_STR + g];
            accum4(a, w1h + k * 20 + v * 5,
                   pack2(hv.x), pack2(hv.y), pack2(hv.z), pack2(hv.w));
        }
        #pragma unroll
        for (int ul = 0; ul < 5; ul++) {
            float hv[4];
            #pragma unroll
            for (int e = 0; e < 4; e++) {
                const ull* ae = a + e * 10;
                float iv = sig_ (getf(ae,      ul));
                float fv = sig_ (getf(ae,  5 + ul));
                float gv = tanh_(getf(ae, 10 + ul));
                float ov = sig_ (getf(ae, 15 + ul));
                float cn = fv * c1[e*5 + ul] + iv * gv;
                c1[e*5 + ul] = cn;
                hv[e] = ov * tanh_(cn);
            }
            hs1[(v * 5 + ul) * HS_STR + g] = make_float4(hv[0], hv[1], hv[2], hv[3]);
        }
        __syncwarp();
    }

    // ---- FC + softmax(2) ----
    float l0 = sm->bfc[0], l1 = sm->bfc[1];
    #pragma unroll
    for (int k = 0; k < H; k++) {
        float4 hq = hs1[k * HS_STR + g];
        float hk = (v == 0) ? hq.x : (v == 1) ? hq.y : (v == 2) ? hq.z : hq.w;
        l0 += sm->wfc[k]     * hk;
        l1 += sm->wfc[H + k] * hk;
    }
    float p0 = sig_(l0 - l1);
    reinterpret_cast<float2*>(out)[bg + v] = make_float2(p0, 1.0f - p0);
}

// ---------------- launch ----------------
extern "C" void kernel_launch(void* const* d_in, const int* in_sizes, int n_in,
                              void* d_out, int out_size) {
    const float* x    = (const float*)d_in[0];
    const float* Wih0 = (const float*)d_in[1];
    const float* Whh0 = (const float*)d_in[2];
    const float* bih0 = (const float*)d_in[3];
    const float* bhh0 = (const float*)d_in[4];
    const float* Wih1 = (const float*)d_in[5];
    const float* Whh1 = (const float*)d_in[6];
    const float* bih1 = (const float*)d_in[7];
    const float* bhh1 = (const float*)d_in[8];
    const float* Wfc  = (const float*)d_in[9];
    const float* bfc  = (const float*)d_in[10];
    float* out = (float*)d_out;

    cudaFuncSetAttribute(xg_gemm_kernel, cudaFuncAttributeMaxDynamicSharedMemorySize, G_SMEM);
    xg_gemm_kernel<<<G_GRID, G_CTA, G_SMEM>>>(x, Wih0, bih0, bhh0);

    const size_t smem2 = sizeof(SMR);
    cudaFuncSetAttribute(lstm2_rec_kernel, cudaFuncAttributeMaxDynamicSharedMemorySize, (int)smem2);
    lstm2_rec_kernel<<<B_TOTAL / CTA, CTA, smem2>>>(
        Whh0, Wih1, Whh1, bih1, bhh1, Wfc, bfc, out);
}